// round 9
// baseline (speedup 1.0000x reference)
#include <cuda_runtime.h>
#include <math.h>
#include <float.h>

// Fixed shape: x [16, 4096, 1024] fp32, gamma/beta [1024].
#define BB 16
#define TT 4096
#define DD 1024
#define KK 8            // NUM_PATTERN
#define PLEN 128        // T/4/NUM_PATTERN
#define MM (KK * PLEN)  // 1024 gathered positions per batch
#define ROWS_PER_BLOCK 8
#define BLOCKS_PER_BATCH (TT / ROWS_PER_BLOCK)   // 512

// Scratch (device globals; no allocation allowed).
__device__ float g_xt[BB * TT];
__device__ float g_xsq[BB * TT];
__device__ float g_maskv[BB * TT];
__device__ float g_mean[BB];
__device__ float g_rinv[BB];
__device__ unsigned int g_cnt[BB];   // zero-initialized; reset by stats block each call

// ---------------------------------------------------------------------------
// Kernel 1 (fused): per-row sum/sumsq, then the LAST block to finish a batch
// computes that batch's peak/top-8/window statistics in-place. Stats for
// batch b overlap the streaming reads of later batches.
// ---------------------------------------------------------------------------
__global__ void rowsum_stats_kernel(const float* __restrict__ x) {
    const int tid  = threadIdx.x;
    const int warp = tid >> 5;
    const int lane = tid & 31;
    const int b    = blockIdx.x / BLOCKS_PER_BATCH;

    // ---- phase 1: row sums (one warp per row, 8 float4 per lane, MLP=8) ----
    {
        int row = blockIdx.x * ROWS_PER_BLOCK + warp;
        const float4* xr = (const float4*)(x + (size_t)row * DD);
        float s = 0.f, ss = 0.f;
#pragma unroll
        for (int i = 0; i < 8; ++i) {
            float4 v = __ldcs(&xr[lane + i * 32]);   // streaming: no reuse in this kernel
            s  += v.x + v.y + v.z + v.w;
            ss += v.x * v.x + v.y * v.y + v.z * v.z + v.w * v.w;
        }
#pragma unroll
        for (int o = 16; o; o >>= 1) {
            s  += __shfl_xor_sync(0xffffffffu, s, o);
            ss += __shfl_xor_sync(0xffffffffu, ss, o);
        }
        if (lane == 0) {
            g_xt[row]  = s;
            g_xsq[row] = ss;
        }
    }

    // ---- arrival: last block of this batch proceeds to stats ----
    __shared__ bool s_last;
    __syncthreads();                     // all 8 rows of this block written
    if (tid == 0) {
        __threadfence();                 // publish row sums
        unsigned old = atomicAdd(&g_cnt[b], 1u);
        s_last = (old == BLOCKS_PER_BATCH - 1);
    }
    __syncthreads();
    if (!s_last) return;
    __threadfence();                     // acquire: other blocks' g_xt/g_xsq

    // ---- phase 2: stats for batch b (256 threads) ----
    __shared__ float              s_xt[TT];              // 16 KB
    __shared__ unsigned int       s_selbits[TT / 32];    // 512 B
    __shared__ int                s_ind[KK];
    __shared__ unsigned long long s_k[8];
    __shared__ double             s_d[8], s_d2[8];

    for (int t = tid; t < TT; t += 256) s_xt[t] = g_xt[b * TT + t];
    for (int w = tid; w < TT / 32; w += 256) s_selbits[w] = 0u;
    __syncthreads();

    // Top-8 of x_points (peak ? xt : 0), tie-break lower index (jax top_k).
    // Key: order-preserving float bits << 32 | (TT-1-t), max-reduced.
    for (int k = 0; k < KK; ++k) {
        unsigned long long best = 0ull;
        for (int t = tid; t < TT; t += 256) {
            float v = s_xt[t];
            float l = (t > 0)      ? s_xt[t - 1] : -FLT_MAX;
            float r = (t < TT - 1) ? s_xt[t + 1] : -FLT_MAX;
            if (v < l || v < r) v = 0.f;         // x_points semantics
            bool taken = false;
#pragma unroll
            for (int j = 0; j < KK; ++j) taken |= (j < k) && (s_ind[j] == t);
            if (taken) continue;
            unsigned ub = __float_as_uint(v);
            ub = (ub & 0x80000000u) ? ~ub : (ub | 0x80000000u);
            unsigned long long key =
                ((unsigned long long)ub << 32) | (unsigned)(TT - 1 - t);
            best = max(best, key);
        }
#pragma unroll
        for (int o = 16; o; o >>= 1)
            best = max(best, __shfl_xor_sync(0xffffffffu, best, o));
        if (lane == 0) s_k[warp] = best;
        __syncthreads();
        if (warp == 0) {
            unsigned long long v = s_k[lane & 7];
#pragma unroll
            for (int o = 4; o; o >>= 1)
                v = max(v, __shfl_xor_sync(0xffffffffu, v, o));
            if (lane == 0) s_ind[k] = TT - 1 - (int)(v & 0xffffffffu);
        }
        __syncthreads();
    }

    // Window gather (duplicates from clipping count multiply, like
    // take_along_axis). Double accumulation for the 2^20-term statistics.
    double s = 0.0, ss = 0.0;
    for (int m = tid; m < MM; m += 256) {
        int k   = m >> 7;
        int o   = (m & 127) - 64;
        int pos = min(max(s_ind[k] + o, 0), TT - 1);
        atomicOr(&s_selbits[pos >> 5], 1u << (pos & 31));
        s  += (double)s_xt[pos];
        ss += (double)g_xsq[b * TT + pos];
    }
#pragma unroll
    for (int o = 16; o; o >>= 1) {
        s  += __shfl_xor_sync(0xffffffffu, s, o);
        ss += __shfl_xor_sync(0xffffffffu, ss, o);
    }
    if (lane == 0) { s_d[warp] = s; s_d2[warp] = ss; }
    __syncthreads();

    if (tid == 0) {
        double S = 0.0, SS = 0.0;
#pragma unroll
        for (int w = 0; w < 8; ++w) { S += s_d[w]; SS += s_d2[w]; }
        double N    = (double)MM * (double)DD;                 // 2^20
        double mean = S / N;
        double var  = (SS - S * S / N) / (N - 1.0);            // ddof=1
        g_mean[b] = (float)mean;
        g_rinv[b] = (float)(1.0 / (sqrt(var) + 1e-8));
        g_cnt[b]  = 0u;                                        // reset for graph replay
    }

    const float mpos = 0.8807970779778823f;    // sigmoid(2.0)
    const float mneg = 0.04742587317756678f;   // sigmoid(-3.0)
    for (int t = tid; t < TT; t += 256)
        g_maskv[b * TT + t] =
            ((s_selbits[t >> 5] >> (t & 31)) & 1u) ? mpos : mneg;
}

// ---------------------------------------------------------------------------
// Kernel 2: out = (gamma*(x-mean)*rinv + beta) * mask[b,t]
// Warp-per-row, 8 float4 per lane (same access shape that hit 84% DRAM),
// streaming hints on both zero-reuse streams.
// ---------------------------------------------------------------------------
__global__ void norm_kernel(const float* __restrict__ x,
                            const float* __restrict__ gamma,
                            const float* __restrict__ beta,
                            float* __restrict__ out) {
    const int warp = threadIdx.x >> 5;
    const int lane = threadIdx.x & 31;
    const int row  = blockIdx.x * ROWS_PER_BLOCK + warp;
    const int b    = row >> 12;

    const float mean = g_mean[b];
    const float a    = g_rinv[b] * g_maskv[row];   // rinv*mask
    const float mv   = g_maskv[row];

    const float4* xr = (const float4*)(x   + (size_t)row * DD);
    float4*       od = (float4*)(out + (size_t)row * DD);
    const float4* g4 = (const float4*)gamma;
    const float4* b4 = (const float4*)beta;

#pragma unroll
    for (int i = 0; i < 8; ++i) {
        int c = lane + i * 32;
        float4 xv = __ldcs(&xr[c]);
        float4 gv = __ldg(&g4[c]);
        float4 bv = __ldg(&b4[c]);
        float4 o;
        o.x = gv.x * (xv.x - mean) * a + bv.x * mv;
        o.y = gv.y * (xv.y - mean) * a + bv.y * mv;
        o.z = gv.z * (xv.z - mean) * a + bv.z * mv;
        o.w = gv.w * (xv.w - mean) * a + bv.w * mv;
        __stcs(&od[c], o);
    }
}

// ---------------------------------------------------------------------------
extern "C" void kernel_launch(void* const* d_in, const int* in_sizes, int n_in,
                              void* d_out, int out_size) {
    const float* x     = (const float*)d_in[0];
    const float* gamma = (const float*)d_in[1];
    const float* beta  = (const float*)d_in[2];
    float*       out   = (float*)d_out;

    rowsum_stats_kernel<<<BB * BLOCKS_PER_BATCH, 256>>>(x);   // 8192 blocks
    norm_kernel<<<BB * TT / ROWS_PER_BLOCK, 256>>>(x, gamma, beta, out);
}

// round 10
// speedup vs baseline: 1.0010x; 1.0010x over previous
#include <cuda_runtime.h>
#include <math.h>
#include <float.h>

// Fixed shape: x [16, 4096, 1024] fp32, gamma/beta [1024].
#define BB 16
#define TT 4096
#define DD 1024
#define KK 8            // NUM_PATTERN
#define PLEN 128        // T/4/NUM_PATTERN
#define MM (KK * PLEN)  // 1024 gathered positions per batch
#define ROWS_PER_BLOCK 8
#define BLOCKS_PER_BATCH (TT / ROWS_PER_BLOCK)   // 512

// Scratch (device globals; no allocation allowed).
__device__ float g_xt[BB * TT];
__device__ float g_xsq[BB * TT];
__device__ float g_maskv[BB * TT];
__device__ float g_mean[BB];
__device__ float g_rinv[BB];
__device__ unsigned int g_cnt[BB];   // zero-initialized; reset by stats block each call

// ---------------------------------------------------------------------------
// Kernel 1 (fused): per-row sum/sumsq, then the LAST block to finish a batch
// computes that batch's peak/top-8/window statistics in-place. Stats for
// batch b overlap the streaming reads of later batches.
// ---------------------------------------------------------------------------
__global__ void rowsum_stats_kernel(const float* __restrict__ x) {
    const int tid  = threadIdx.x;
    const int warp = tid >> 5;
    const int lane = tid & 31;
    const int b    = blockIdx.x / BLOCKS_PER_BATCH;

    // ---- phase 1: row sums (one warp per row, 8 float4 per lane, MLP=8) ----
    {
        int row = blockIdx.x * ROWS_PER_BLOCK + warp;
        const float4* xr = (const float4*)(x + (size_t)row * DD);
        float s = 0.f, ss = 0.f;
#pragma unroll
        for (int i = 0; i < 8; ++i) {
            float4 v = __ldcs(&xr[lane + i * 32]);   // streaming: no reuse in this kernel
            s  += v.x + v.y + v.z + v.w;
            ss += v.x * v.x + v.y * v.y + v.z * v.z + v.w * v.w;
        }
#pragma unroll
        for (int o = 16; o; o >>= 1) {
            s  += __shfl_xor_sync(0xffffffffu, s, o);
            ss += __shfl_xor_sync(0xffffffffu, ss, o);
        }
        if (lane == 0) {
            g_xt[row]  = s;
            g_xsq[row] = ss;
        }
    }

    // ---- arrival: last block of this batch proceeds to stats ----
    __shared__ bool s_last;
    __syncthreads();                     // all 8 rows of this block written
    if (tid == 0) {
        __threadfence();                 // publish row sums
        unsigned old = atomicAdd(&g_cnt[b], 1u);
        s_last = (old == BLOCKS_PER_BATCH - 1);
    }
    __syncthreads();
    if (!s_last) return;
    __threadfence();                     // acquire: other blocks' g_xt/g_xsq

    // ---- phase 2: stats for batch b (256 threads) ----
    __shared__ float              s_xt[TT];              // 16 KB
    __shared__ unsigned int       s_selbits[TT / 32];    // 512 B
    __shared__ int                s_ind[KK];
    __shared__ unsigned long long s_k[8];
    __shared__ double             s_d[8], s_d2[8];

    for (int t = tid; t < TT; t += 256) s_xt[t] = g_xt[b * TT + t];
    for (int w = tid; w < TT / 32; w += 256) s_selbits[w] = 0u;
    __syncthreads();

    // Top-8 of x_points (peak ? xt : 0), tie-break lower index (jax top_k).
    // Key: order-preserving float bits << 32 | (TT-1-t), max-reduced.
    for (int k = 0; k < KK; ++k) {
        unsigned long long best = 0ull;
        for (int t = tid; t < TT; t += 256) {
            float v = s_xt[t];
            float l = (t > 0)      ? s_xt[t - 1] : -FLT_MAX;
            float r = (t < TT - 1) ? s_xt[t + 1] : -FLT_MAX;
            if (v < l || v < r) v = 0.f;         // x_points semantics
            bool taken = false;
#pragma unroll
            for (int j = 0; j < KK; ++j) taken |= (j < k) && (s_ind[j] == t);
            if (taken) continue;
            unsigned ub = __float_as_uint(v);
            ub = (ub & 0x80000000u) ? ~ub : (ub | 0x80000000u);
            unsigned long long key =
                ((unsigned long long)ub << 32) | (unsigned)(TT - 1 - t);
            best = max(best, key);
        }
#pragma unroll
        for (int o = 16; o; o >>= 1)
            best = max(best, __shfl_xor_sync(0xffffffffu, best, o));
        if (lane == 0) s_k[warp] = best;
        __syncthreads();
        if (warp == 0) {
            unsigned long long v = s_k[lane & 7];
#pragma unroll
            for (int o = 4; o; o >>= 1)
                v = max(v, __shfl_xor_sync(0xffffffffu, v, o));
            if (lane == 0) s_ind[k] = TT - 1 - (int)(v & 0xffffffffu);
        }
        __syncthreads();
    }

    // Window gather (duplicates from clipping count multiply, like
    // take_along_axis). Double accumulation for the 2^20-term statistics.
    double s = 0.0, ss = 0.0;
    for (int m = tid; m < MM; m += 256) {
        int k   = m >> 7;
        int o   = (m & 127) - 64;
        int pos = min(max(s_ind[k] + o, 0), TT - 1);
        atomicOr(&s_selbits[pos >> 5], 1u << (pos & 31));
        s  += (double)s_xt[pos];
        ss += (double)g_xsq[b * TT + pos];
    }
#pragma unroll
    for (int o = 16; o; o >>= 1) {
        s  += __shfl_xor_sync(0xffffffffu, s, o);
        ss += __shfl_xor_sync(0xffffffffu, ss, o);
    }
    if (lane == 0) { s_d[warp] = s; s_d2[warp] = ss; }
    __syncthreads();

    if (tid == 0) {
        double S = 0.0, SS = 0.0;
#pragma unroll
        for (int w = 0; w < 8; ++w) { S += s_d[w]; SS += s_d2[w]; }
        double N    = (double)MM * (double)DD;                 // 2^20
        double mean = S / N;
        double var  = (SS - S * S / N) / (N - 1.0);            // ddof=1
        g_mean[b] = (float)mean;
        g_rinv[b] = (float)(1.0 / (sqrt(var) + 1e-8));
        g_cnt[b]  = 0u;                                        // reset for graph replay
    }

    const float mpos = 0.8807970779778823f;    // sigmoid(2.0)
    const float mneg = 0.04742587317756678f;   // sigmoid(-3.0)
    for (int t = tid; t < TT; t += 256)
        g_maskv[b * TT + t] =
            ((s_selbits[t >> 5] >> (t & 31)) & 1u) ? mpos : mneg;
}

// ---------------------------------------------------------------------------
// Kernel 2: out = (gamma*(x-mean)*rinv + beta) * mask[b,t]
// Warp-per-row, 8 float4 per lane (same access shape that hit 84% DRAM),
// streaming hints on both zero-reuse streams.
// ---------------------------------------------------------------------------
__global__ void norm_kernel(const float* __restrict__ x,
                            const float* __restrict__ gamma,
                            const float* __restrict__ beta,
                            float* __restrict__ out) {
    const int warp = threadIdx.x >> 5;
    const int lane = threadIdx.x & 31;
    const int row  = blockIdx.x * ROWS_PER_BLOCK + warp;
    const int b    = row >> 12;

    const float mean = g_mean[b];
    const float a    = g_rinv[b] * g_maskv[row];   // rinv*mask
    const float mv   = g_maskv[row];

    const float4* xr = (const float4*)(x   + (size_t)row * DD);
    float4*       od = (float4*)(out + (size_t)row * DD);
    const float4* g4 = (const float4*)gamma;
    const float4* b4 = (const float4*)beta;

#pragma unroll
    for (int i = 0; i < 8; ++i) {
        int c = lane + i * 32;
        float4 xv = __ldcs(&xr[c]);
        float4 gv = __ldg(&g4[c]);
        float4 bv = __ldg(&b4[c]);
        float4 o;
        o.x = gv.x * (xv.x - mean) * a + bv.x * mv;
        o.y = gv.y * (xv.y - mean) * a + bv.y * mv;
        o.z = gv.z * (xv.z - mean) * a + bv.z * mv;
        o.w = gv.w * (xv.w - mean) * a + bv.w * mv;
        __stcs(&od[c], o);
    }
}

// ---------------------------------------------------------------------------
extern "C" void kernel_launch(void* const* d_in, const int* in_sizes, int n_in,
                              void* d_out, int out_size) {
    const float* x     = (const float*)d_in[0];
    const float* gamma = (const float*)d_in[1];
    const float* beta  = (const float*)d_in[2];
    float*       out   = (float*)d_out;

    rowsum_stats_kernel<<<BB * BLOCKS_PER_BATCH, 256>>>(x);   // 8192 blocks
    norm_kernel<<<BB * TT / ROWS_PER_BLOCK, 256>>>(x, gamma, beta, out);
}

// round 11
// speedup vs baseline: 1.0013x; 1.0002x over previous
#include <cuda_runtime.h>
#include <math.h>
#include <float.h>

// Fixed shape: x [16, 4096, 1024] fp32, gamma/beta [1024].
#define BB 16
#define TT 4096
#define DD 1024
#define KK 8            // NUM_PATTERN
#define PLEN 128        // T/4/NUM_PATTERN
#define MM (KK * PLEN)  // 1024 gathered positions per batch
#define ROWS_PER_BLOCK 8
#define BLOCKS_PER_BATCH (TT / ROWS_PER_BLOCK)   // 512

// Scratch (device globals; no allocation allowed).
__device__ float g_xt[BB * TT];
__device__ float g_xsq[BB * TT];
__device__ float g_maskv[BB * TT];
__device__ float g_mean[BB];
__device__ float g_rinv[BB];
__device__ unsigned int g_cnt[BB];   // zero-initialized; reset by stats block each call

// ---------------------------------------------------------------------------
// Kernel 1 (fused): per-row sum/sumsq, then the LAST block to finish a batch
// computes that batch's peak/top-8/window statistics in-place. Stats for
// batch b overlap the streaming reads of later batches.
// ---------------------------------------------------------------------------
__global__ void rowsum_stats_kernel(const float* __restrict__ x) {
    const int tid  = threadIdx.x;
    const int warp = tid >> 5;
    const int lane = tid & 31;
    const int b    = blockIdx.x / BLOCKS_PER_BATCH;

    // ---- phase 1: row sums (one warp per row, 8 float4 per lane, MLP=8) ----
    {
        int row = blockIdx.x * ROWS_PER_BLOCK + warp;
        const float4* xr = (const float4*)(x + (size_t)row * DD);
        float s = 0.f, ss = 0.f;
#pragma unroll
        for (int i = 0; i < 8; ++i) {
            float4 v = __ldcs(&xr[lane + i * 32]);   // streaming: no reuse in this kernel
            s  += v.x + v.y + v.z + v.w;
            ss += v.x * v.x + v.y * v.y + v.z * v.z + v.w * v.w;
        }
#pragma unroll
        for (int o = 16; o; o >>= 1) {
            s  += __shfl_xor_sync(0xffffffffu, s, o);
            ss += __shfl_xor_sync(0xffffffffu, ss, o);
        }
        if (lane == 0) {
            g_xt[row]  = s;
            g_xsq[row] = ss;
        }
    }

    // ---- arrival: last block of this batch proceeds to stats ----
    __shared__ bool s_last;
    __syncthreads();                     // all 8 rows of this block written
    if (tid == 0) {
        __threadfence();                 // publish row sums
        unsigned old = atomicAdd(&g_cnt[b], 1u);
        s_last = (old == BLOCKS_PER_BATCH - 1);
    }
    __syncthreads();
    if (!s_last) return;
    __threadfence();                     // acquire: other blocks' g_xt/g_xsq

    // ---- phase 2: stats for batch b (256 threads) ----
    __shared__ float              s_xt[TT];              // 16 KB
    __shared__ unsigned int       s_selbits[TT / 32];    // 512 B
    __shared__ int                s_ind[KK];
    __shared__ unsigned long long s_k[8];
    __shared__ double             s_d[8], s_d2[8];

    for (int t = tid; t < TT; t += 256) s_xt[t] = g_xt[b * TT + t];
    for (int w = tid; w < TT / 32; w += 256) s_selbits[w] = 0u;
    __syncthreads();

    // Top-8 of x_points (peak ? xt : 0), tie-break lower index (jax top_k).
    // Key: order-preserving float bits << 32 | (TT-1-t), max-reduced.
    for (int k = 0; k < KK; ++k) {
        unsigned long long best = 0ull;
        for (int t = tid; t < TT; t += 256) {
            float v = s_xt[t];
            float l = (t > 0)      ? s_xt[t - 1] : -FLT_MAX;
            float r = (t < TT - 1) ? s_xt[t + 1] : -FLT_MAX;
            if (v < l || v < r) v = 0.f;         // x_points semantics
            bool taken = false;
#pragma unroll
            for (int j = 0; j < KK; ++j) taken |= (j < k) && (s_ind[j] == t);
            if (taken) continue;
            unsigned ub = __float_as_uint(v);
            ub = (ub & 0x80000000u) ? ~ub : (ub | 0x80000000u);
            unsigned long long key =
                ((unsigned long long)ub << 32) | (unsigned)(TT - 1 - t);
            best = max(best, key);
        }
#pragma unroll
        for (int o = 16; o; o >>= 1)
            best = max(best, __shfl_xor_sync(0xffffffffu, best, o));
        if (lane == 0) s_k[warp] = best;
        __syncthreads();
        if (warp == 0) {
            unsigned long long v = s_k[lane & 7];
#pragma unroll
            for (int o = 4; o; o >>= 1)
                v = max(v, __shfl_xor_sync(0xffffffffu, v, o));
            if (lane == 0) s_ind[k] = TT - 1 - (int)(v & 0xffffffffu);
        }
        __syncthreads();
    }

    // Window gather (duplicates from clipping count multiply, like
    // take_along_axis). Double accumulation for the 2^20-term statistics.
    double s = 0.0, ss = 0.0;
    for (int m = tid; m < MM; m += 256) {
        int k   = m >> 7;
        int o   = (m & 127) - 64;
        int pos = min(max(s_ind[k] + o, 0), TT - 1);
        atomicOr(&s_selbits[pos >> 5], 1u << (pos & 31));
        s  += (double)s_xt[pos];
        ss += (double)g_xsq[b * TT + pos];
    }
#pragma unroll
    for (int o = 16; o; o >>= 1) {
        s  += __shfl_xor_sync(0xffffffffu, s, o);
        ss += __shfl_xor_sync(0xffffffffu, ss, o);
    }
    if (lane == 0) { s_d[warp] = s; s_d2[warp] = ss; }
    __syncthreads();

    if (tid == 0) {
        double S = 0.0, SS = 0.0;
#pragma unroll
        for (int w = 0; w < 8; ++w) { S += s_d[w]; SS += s_d2[w]; }
        double N    = (double)MM * (double)DD;                 // 2^20
        double mean = S / N;
        double var  = (SS - S * S / N) / (N - 1.0);            // ddof=1
        g_mean[b] = (float)mean;
        g_rinv[b] = (float)(1.0 / (sqrt(var) + 1e-8));
        g_cnt[b]  = 0u;                                        // reset for graph replay
    }

    const float mpos = 0.8807970779778823f;    // sigmoid(2.0)
    const float mneg = 0.04742587317756678f;   // sigmoid(-3.0)
    for (int t = tid; t < TT; t += 256)
        g_maskv[b * TT + t] =
            ((s_selbits[t >> 5] >> (t & 31)) & 1u) ? mpos : mneg;
}

// ---------------------------------------------------------------------------
// Kernel 2: out = (gamma*(x-mean)*rinv + beta) * mask[b,t]
// Warp-per-row, 8 float4 per lane (same access shape that hit 84% DRAM),
// streaming hints on both zero-reuse streams.
// ---------------------------------------------------------------------------
__global__ void norm_kernel(const float* __restrict__ x,
                            const float* __restrict__ gamma,
                            const float* __restrict__ beta,
                            float* __restrict__ out) {
    const int warp = threadIdx.x >> 5;
    const int lane = threadIdx.x & 31;
    const int row  = blockIdx.x * ROWS_PER_BLOCK + warp;
    const int b    = row >> 12;

    const float mean = g_mean[b];
    const float a    = g_rinv[b] * g_maskv[row];   // rinv*mask
    const float mv   = g_maskv[row];

    const float4* xr = (const float4*)(x   + (size_t)row * DD);
    float4*       od = (float4*)(out + (size_t)row * DD);
    const float4* g4 = (const float4*)gamma;
    const float4* b4 = (const float4*)beta;

#pragma unroll
    for (int i = 0; i < 8; ++i) {
        int c = lane + i * 32;
        float4 xv = __ldcs(&xr[c]);
        float4 gv = __ldg(&g4[c]);
        float4 bv = __ldg(&b4[c]);
        float4 o;
        o.x = gv.x * (xv.x - mean) * a + bv.x * mv;
        o.y = gv.y * (xv.y - mean) * a + bv.y * mv;
        o.z = gv.z * (xv.z - mean) * a + bv.z * mv;
        o.w = gv.w * (xv.w - mean) * a + bv.w * mv;
        __stcs(&od[c], o);
    }
}

// ---------------------------------------------------------------------------
extern "C" void kernel_launch(void* const* d_in, const int* in_sizes, int n_in,
                              void* d_out, int out_size) {
    const float* x     = (const float*)d_in[0];
    const float* gamma = (const float*)d_in[1];
    const float* beta  = (const float*)d_in[2];
    float*       out   = (float*)d_out;

    rowsum_stats_kernel<<<BB * BLOCKS_PER_BATCH, 256>>>(x);   // 8192 blocks
    norm_kernel<<<BB * TT / ROWS_PER_BLOCK, 256>>>(x, gamma, beta, out);
}